// round 16
// baseline (speedup 1.0000x reference)
#include <cuda_runtime.h>
#include <cuda_fp16.h>
#include <math.h>
#include <stdint.h>

// ---------------------------------------------------------------------------
// Problem constants
// ---------------------------------------------------------------------------
#define BATCH     4
#define SEQ       4096
#define DMODEL    1024
#define HEADS     2
#define DEPTH     512
#define MFEAT     256
#define ROWS      (BATCH*SEQ)          // 16384
#define ROWS2     (ROWS*HEADS)         // 32768

#define SCALE2    0.044194173824159216f   // 1/sqrt(512)
#define FSCALE    0.21022410381342864f    // 512^{-0.25}
#define RATIO     0.0625f                 // 1/sqrt(256)
#define EPS       1e-6f

// ---------------------------------------------------------------------------
// Scratch (device globals; allocation is banned)
// ---------------------------------------------------------------------------
__device__ __half g_dQh[ (size_t)ROWS2 * MFEAT ];    // fp16 dash_q
__device__ __half g_dKh[ (size_t)ROWS2 * MFEAT ];    // fp16 dash_k
__device__ float  g_diagQ[ ROWS2 ];
__device__ float  g_diagK[ ROWS2 ];
__device__ float  g_rmxp [ 4 * ROWS2 ];              // per-colblock rowmax partials
__device__ float  g_kmax [ BATCH*HEADS ];
__device__ float  g_sqpQ[ 16 * ROWS ];               // per-colblock Σy² partials (Q)
__device__ float  g_sqpK[ 16 * ROWS ];               // (K)
__device__ __half g_A0 [ (size_t)ROWS * DMODEL ];    // fp16 query
__device__ __half g_A1 [ (size_t)ROWS * DMODEL ];    // fp16 key
__device__ __half g_A2 [ (size_t)ROWS * DMODEL ];    // fp16 value
__device__ __half g_Qh [ (size_t)ROWS * DMODEL ];    // fp16 Q
__device__ __half g_Kh [ (size_t)ROWS * DMODEL ];    // fp16 K
__device__ __half g_Vh [ (size_t)ROWS * DMODEL ];    // fp16 V
__device__ __half g_W0 [ (size_t)DMODEL * DMODEL ];  // fp16 Wq^T
__device__ __half g_W1 [ (size_t)DMODEL * DMODEL ];  // fp16 Wk^T
__device__ __half g_W2 [ (size_t)DMODEL * DMODEL ];  // fp16 Wv^T
__device__ __half g_W3 [ (size_t)DMODEL * DMODEL ];  // fp16 Wo^T
__device__ __half g_fh [ (size_t)MFEAT * DEPTH ];    // fp16 feats
__device__ __half g_Ch [ (size_t)ROWS * DMODEL ];    // fp16 concat

// ---------------------------------------------------------------------------
// helpers
// ---------------------------------------------------------------------------
__device__ __forceinline__ uint32_t smem_u32(const void* p) {
    uint32_t a;
    asm("{ .reg .u64 t; cvta.to.shared.u64 t, %1; cvt.u32.u64 %0, t; }"
        : "=r"(a) : "l"(p));
    return a;
}

__device__ __forceinline__ void ldsm_x4(uint32_t& r0, uint32_t& r1,
                                        uint32_t& r2, uint32_t& r3, uint32_t addr) {
    asm volatile("ldmatrix.sync.aligned.m8n8.x4.shared.b16 {%0,%1,%2,%3}, [%4];"
                 : "=r"(r0), "=r"(r1), "=r"(r2), "=r"(r3) : "r"(addr));
}

__device__ __forceinline__ void mma_f16(float c[4], const uint32_t a[4],
                                        const uint32_t b[2]) {
    asm volatile(
        "mma.sync.aligned.m16n8k16.row.col.f32.f16.f16.f32 "
        "{%0,%1,%2,%3}, {%4,%5,%6,%7}, {%8,%9}, {%0,%1,%2,%3};"
        : "+f"(c[0]), "+f"(c[1]), "+f"(c[2]), "+f"(c[3])
        : "r"(a[0]), "r"(a[1]), "r"(a[2]), "r"(a[3]),
          "r"(b[0]), "r"(b[1]));
}

__device__ __forceinline__ void cp_async16(uint32_t smem, const void* gmem) {
    asm volatile("cp.async.cg.shared.global [%0], [%1], 16;"
                 :: "r"(smem), "l"(gmem) : "memory");
}
#define CP_COMMIT()  asm volatile("cp.async.commit_group;" ::: "memory")
#define CP_WAIT0()   asm volatile("cp.async.wait_group 0;" ::: "memory")

// ---------------------------------------------------------------------------
// Batched fp16 GEMM jobs (selected by blockIdx.z)
// ---------------------------------------------------------------------------
struct GemmJob {
    const __half* A;      // [M,K]
    const __half* Bop;    // [N,K]
    const float*  bias;   // [N] or null
    float*        C;      // fp32 out or null
    __half*       Ch;     // fp16 out or null
    float*        sq;     // per-row sum-sq partials [N/64][M] or null
    float*        rmx;    // per-row max partials [N/64][M] or null
};
struct GemmJobs { GemmJob j[3]; };

// ---------------------------------------------------------------------------
// fp16 GEMM (fp32 accumulate):  C = alpha * A(M,K) @ Bop(N,K)^T (+ bias)
//   128 threads/CTA, tile 128(M) x 64(N), warp tile 64x32 (2x2 warps),
//   2-stage cp.async pipeline, K-step 64, A-fragment double buffering.
//   Requires M%128, N%64, K%64==0, K>=128.   (R13 config — best measured)
// ---------------------------------------------------------------------------
#define ASTR   72                       // halves per row: 64 + 8 pad (144B)
#define STG_A  (128*ASTR)               // 9216 halves
#define STG_B  (64*ASTR)                // 4608 halves
#define STG_T  (STG_A + STG_B)          // 13824 halves / stage
#define HSMEM  (2 * STG_T * 2)          // bytes = 55296

__global__ __launch_bounds__(128, 4)
void hgemm(GemmJobs jobs, int M, int N, int K, float alpha)
{
    extern __shared__ __half sm[];
    const GemmJob job = jobs.j[blockIdx.z];
    const __half* __restrict__ A   = job.A;
    const __half* __restrict__ Bop = job.Bop;

    const int tid  = threadIdx.x;
    const int lane = tid & 31;
    const int wid  = tid >> 5;            // 0..3
    const int bm = blockIdx.y * 128;
    const int bn = blockIdx.x * 64;

    const int warp_m = (wid & 1) * 64;
    const int warp_n = (wid >> 1) * 32;
    const int lr = lane >> 2;
    const int lc = lane & 3;

    const uint32_t smb = smem_u32(sm);

    auto issue_stage = [&](int s, int k0) {
        const int slot = s & 1;
        const uint32_t abase = smb + (uint32_t)(slot * STG_T) * 2;
        const uint32_t bbase = abase + (uint32_t)STG_A * 2;
        #pragma unroll
        for (int c = 0; c < 8; c++) {
            int chunk = tid + 128 * c;
            int row = chunk >> 3;
            int col = (chunk & 7) * 8;
            cp_async16(abase + (uint32_t)(row * ASTR + col) * 2,
                       A + (size_t)(bm + row) * K + k0 + col);
        }
        #pragma unroll
        for (int c = 0; c < 4; c++) {
            int chunk = tid + 128 * c;
            int row = chunk >> 3;
            int col = (chunk & 7) * 8;
            cp_async16(bbase + (uint32_t)(row * ASTR + col) * 2,
                       Bop + (size_t)(bn + row) * K + k0 + col);
        }
        CP_COMMIT();
    };

    float acc[4][4][4];
    #pragma unroll
    for (int i = 0; i < 4; i++)
        #pragma unroll
        for (int j = 0; j < 4; j++)
            #pragma unroll
            for (int r = 0; r < 4; r++) acc[i][j][r] = 0.f;

    const int a_lrow = (lane & 7) + ((lane >> 3) & 1) * 8;
    const int a_lcol = (lane >> 4) * 8;
    const int b_lrow = (lane & 7) + (lane >= 16 ? 8 : 0);
    const int b_lcol = ((lane >> 3) & 1) * 8;

    const int nst = K >> 6;
    issue_stage(0, 0);

    for (int s = 0; s < nst; s++) {
        CP_WAIT0();
        __syncthreads();

        if (s + 1 < nst) issue_stage(s + 1, (s + 1) << 6);

        const __half* As = sm + (s & 1) * STG_T;
        const __half* Bs = As + STG_A;

        uint32_t fa[2][4][4];
        #pragma unroll
        for (int mi = 0; mi < 4; mi++) {
            uint32_t addr = smem_u32(
                &As[(warp_m + mi * 16 + a_lrow) * ASTR + a_lcol]);
            ldsm_x4(fa[0][mi][0], fa[0][mi][1], fa[0][mi][2], fa[0][mi][3], addr);
        }

        #pragma unroll
        for (int kk = 0; kk < 4; kk++) {
            const int pb = kk & 1;
            uint32_t fb[4][2];
            #pragma unroll
            for (int nj = 0; nj < 2; nj++) {
                uint32_t addr = smem_u32(
                    &Bs[(warp_n + nj * 16 + b_lrow) * ASTR + kk * 16 + b_lcol]);
                ldsm_x4(fb[2*nj][0], fb[2*nj][1], fb[2*nj+1][0], fb[2*nj+1][1], addr);
            }
            if (kk < 3) {
                #pragma unroll
                for (int mi = 0; mi < 4; mi++) {
                    uint32_t addr = smem_u32(
                        &As[(warp_m + mi * 16 + a_lrow) * ASTR + (kk + 1) * 16 + a_lcol]);
                    ldsm_x4(fa[pb^1][mi][0], fa[pb^1][mi][1],
                            fa[pb^1][mi][2], fa[pb^1][mi][3], addr);
                }
            }
            #pragma unroll
            for (int mi = 0; mi < 4; mi++)
                #pragma unroll
                for (int ni = 0; ni < 4; ni++)
                    mma_f16(acc[mi][ni], fa[pb][mi], fb[ni]);
        }
    }

    // epilogue (+ optional per-row Σv² / rowmax partials)
    float sA[4], sB[4], mA[4], mB[4];
    #pragma unroll
    for (int mi = 0; mi < 4; mi++) {
        sA[mi] = 0.f; sB[mi] = 0.f; mA[mi] = -1e30f; mB[mi] = -1e30f;
    }

    #pragma unroll
    for (int mi = 0; mi < 4; mi++) {
        #pragma unroll
        for (int ni = 0; ni < 4; ni++) {
            int row = bm + warp_m + mi * 16 + lr;
            int col = bn + warp_n + ni * 8 + 2 * lc;
            float b0 = job.bias ? job.bias[col]     : 0.f;
            float b1 = job.bias ? job.bias[col + 1] : 0.f;
            float2 v0 = make_float2(alpha * acc[mi][ni][0] + b0,
                                    alpha * acc[mi][ni][1] + b1);
            float2 v1 = make_float2(alpha * acc[mi][ni][2] + b0,
                                    alpha * acc[mi][ni][3] + b1);
            if (job.C) {
                *reinterpret_cast<float2*>(&job.C[(size_t)row * N + col])       = v0;
                *reinterpret_cast<float2*>(&job.C[(size_t)(row + 8) * N + col]) = v1;
            }
            if (job.Ch) {
                *reinterpret_cast<__half2*>(&job.Ch[(size_t)row * N + col]) =
                    __floats2half2_rn(v0.x, v0.y);
                *reinterpret_cast<__half2*>(&job.Ch[(size_t)(row + 8) * N + col]) =
                    __floats2half2_rn(v1.x, v1.y);
            }
            if (job.sq) {
                sA[mi] += v0.x * v0.x + v0.y * v0.y;
                sB[mi] += v1.x * v1.x + v1.y * v1.y;
            }
            if (job.rmx) {
                mA[mi] = fmaxf(mA[mi], fmaxf(v0.x, v0.y));
                mB[mi] = fmaxf(mB[mi], fmaxf(v1.x, v1.y));
            }
        }
    }

    float* smf = reinterpret_cast<float*>(sm);  // [2][128] floats
    if (job.sq) {
        #pragma unroll
        for (int mi = 0; mi < 4; mi++) {
            #pragma unroll
            for (int o = 1; o <= 2; o <<= 1) {
                sA[mi] += __shfl_xor_sync(0xffffffff, sA[mi], o);
                sB[mi] += __shfl_xor_sync(0xffffffff, sB[mi], o);
            }
        }
        __syncthreads();
        if (lc == 0) {
            #pragma unroll
            for (int mi = 0; mi < 4; mi++) {
                smf[(wid >> 1) * 128 + warp_m + mi * 16 + lr]     = sA[mi];
                smf[(wid >> 1) * 128 + warp_m + mi * 16 + lr + 8] = sB[mi];
            }
        }
        __syncthreads();
        {
            float t = smf[tid] + smf[128 + tid];
            job.sq[(size_t)blockIdx.x * M + bm + tid] = t;
        }
    }
    if (job.rmx) {
        #pragma unroll
        for (int mi = 0; mi < 4; mi++) {
            #pragma unroll
            for (int o = 1; o <= 2; o <<= 1) {
                mA[mi] = fmaxf(mA[mi], __shfl_xor_sync(0xffffffff, mA[mi], o));
                mB[mi] = fmaxf(mB[mi], __shfl_xor_sync(0xffffffff, mB[mi], o));
            }
        }
        __syncthreads();
        if (lc == 0) {
            #pragma unroll
            for (int mi = 0; mi < 4; mi++) {
                smf[(wid >> 1) * 128 + warp_m + mi * 16 + lr]     = mA[mi];
                smf[(wid >> 1) * 128 + warp_m + mi * 16 + lr + 8] = mB[mi];
            }
        }
        __syncthreads();
        {
            float t = fmaxf(smf[tid], smf[128 + tid]);
            job.rmx[(size_t)blockIdx.x * M + bm + tid] = t;
        }
    }
}

// ---------------------------------------------------------------------------
// diag reduce: diag[r*2+h] = 0.5*SCALE2 * sum_{j<8} part[(h*8+j)*ROWS + r]
// ---------------------------------------------------------------------------
__global__ __launch_bounds__(256)
void sqreduce_kernel(const float* __restrict__ partQ, float* __restrict__ diagQ,
                     const float* __restrict__ partK, float* __restrict__ diagK)
{
    int r2 = blockIdx.x * blockDim.x + threadIdx.x;
    if (r2 >= ROWS2) return;
    int r = r2 >> 1, h = r2 & 1;
    {
        const float* p = partQ + (size_t)(h * 8) * ROWS + r;
        float s = 0.f;
        #pragma unroll
        for (int j = 0; j < 8; j++) s += p[(size_t)j * ROWS];
        diagQ[r2] = 0.5f * SCALE2 * s;
    }
    {
        const float* p = partK + (size_t)(h * 8) * ROWS + r;
        float s = 0.f;
        #pragma unroll
        for (int j = 0; j < 8; j++) s += p[(size_t)j * ROWS];
        diagK[r2] = 0.5f * SCALE2 * s;
    }
}

// ---------------------------------------------------------------------------
// kmax: per (b,h) global max over sequence of dK rowmax partials (4 colblocks)
// ---------------------------------------------------------------------------
__global__ __launch_bounds__(256)
void kmax_kernel(const float* __restrict__ rmxp, float* __restrict__ kmax)
{
    int bh = blockIdx.x;
    int b  = bh >> 1, h = bh & 1;
    __shared__ float sm[256];
    float mx = -1e30f;
    for (int l = threadIdx.x; l < SEQ; l += 256) {
        int r = b * 8192 + l * 2 + h;
        #pragma unroll
        for (int cb = 0; cb < 4; cb++)
            mx = fmaxf(mx, rmxp[(size_t)cb * ROWS2 + r]);
    }
    sm[threadIdx.x] = mx;
    __syncthreads();
    for (int s = 128; s; s >>= 1) {
        if (threadIdx.x < s) sm[threadIdx.x] = fmaxf(sm[threadIdx.x], sm[threadIdx.x + s]);
        __syncthreads();
    }
    if (threadIdx.x == 0) kmax[bh] = sm[0];
}

// ---------------------------------------------------------------------------
// Merged conversion kernel: all fp16 prep in ONE launch.
//   CTAs [0, 3*8192)         : f2h of query/key/value (8192 CTAs each)
//   CTAs [24576, 24576+4096) : transpose+convert of Wq/Wk/Wv/Wo (1024 each)
//   CTAs [28672, 28672+64)   : f2h of feats
// ---------------------------------------------------------------------------
#define CONV_F2H_CTAS   (3 * 8192)
#define CONV_TC_CTAS    (4 * 1024)
#define CONV_FEAT_CTAS  64
#define CONV_TOTAL      (CONV_F2H_CTAS + CONV_TC_CTAS + CONV_FEAT_CTAS)

struct ConvArgs {
    const float* in3[3];  __half* out3[3];     // inputs
    const float* w[4];    __half* wo[4];       // weights
    const float* feats;   __half* fh;
};

__global__ __launch_bounds__(256)
void convert_all_kernel(ConvArgs a)
{
    __shared__ float tile[32][33];
    int cta = blockIdx.x;
    int tid = threadIdx.x;

    if (cta < CONV_F2H_CTAS) {
        int which = cta / 8192;
        int local = cta - which * 8192;
        const float* in  = a.in3[which];
        __half*      out = a.out3[which];
        size_t i = ((size_t)local * 256 + tid) * 8;
        float4 v0 = *reinterpret_cast<const float4*>(in + i);
        float4 v1 = *reinterpret_cast<const float4*>(in + i + 4);
        __half h[8];
        h[0]=__float2half_rn(v0.x); h[1]=__float2half_rn(v0.y);
        h[2]=__float2half_rn(v0.z); h[3]=__float2half_rn(v0.w);
        h[4]=__float2half_rn(v1.x); h[5]=__float2half_rn(v1.y);
        h[6]=__float2half_rn(v1.z); h[7]=__float2half_rn(v1.w);
        *reinterpret_cast<uint4*>(out + i) = *reinterpret_cast<uint4*>(h);
        return;
    }
    cta -= CONV_F2H_CTAS;
    if (cta < CONV_TC_CTAS) {
        int z     = cta >> 10;          // 0..3
        int rem   = cta & 1023;
        int bx    = (rem & 31) * 32;
        int by    = (rem >> 5) * 32;
        const float* in  = a.w[z];
        __half*      out = a.wo[z];
        int tx = tid & 31;
        int ty = tid >> 5;
        #pragma unroll
        for (int i = 0; i < 32; i += 8)
            tile[ty + i][tx] = in[(size_t)(by + ty + i) * DMODEL + bx + tx];
        __syncthreads();
        #pragma unroll
        for (int i = 0; i < 32; i += 8)
            out[(size_t)(bx + ty + i) * DMODEL + by + tx] =
                __float2half_rn(tile[tx][ty + i]);
        return;
    }
    cta -= CONV_TC_CTAS;
    {
        size_t i = ((size_t)cta * 256 + tid) * 8;
        float4 v0 = *reinterpret_cast<const float4*>(a.feats + i);
        float4 v1 = *reinterpret_cast<const float4*>(a.feats + i + 4);
        __half h[8];
        h[0]=__float2half_rn(v0.x); h[1]=__float2half_rn(v0.y);
        h[2]=__float2half_rn(v0.z); h[3]=__float2half_rn(v0.w);
        h[4]=__float2half_rn(v1.x); h[5]=__float2half_rn(v1.y);
        h[6]=__float2half_rn(v1.z); h[7]=__float2half_rn(v1.w);
        *reinterpret_cast<uint4*>(a.fh + i) = *reinterpret_cast<uint4*>(h);
    }
}

// ---------------------------------------------------------------------------
// Attention mix (fused q'/k'): per (s,h) block. fp16 dash in, __expf.
// ---------------------------------------------------------------------------
__global__ __launch_bounds__(256)
void attn_mix_kernel(const __half* __restrict__ dQ, const __half* __restrict__ dK,
                     const float* __restrict__ diagQ, const float* __restrict__ diagK,
                     const float* __restrict__ kmax,
                     const __half* __restrict__ Vh, __half* __restrict__ C)
{
    int blk = blockIdx.x;
    int s = blk >> 1, h = blk & 1;
    __shared__ float q_s[4][MFEAT];
    __shared__ float k_s[4][MFEAT];
    __shared__ float red[4][8];
    __shared__ float S[4][4];
    __shared__ float rs[4];
    int tid = threadIdx.x;
    int wid = tid >> 5, lane = tid & 31;

    float qv[4], kv[4];
    int ridx[4];
    #pragma unroll
    for (int bb = 0; bb < 4; bb++) {
        size_t r = (size_t)((bb*SEQ + s)*HEADS + h);
        ridx[bb] = (int)r;
        qv[bb] = __half2float(dQ[r*MFEAT + tid]);
        kv[bb] = __half2float(dK[r*MFEAT + tid]);
    }
    #pragma unroll
    for (int bb = 0; bb < 4; bb++) {
        float m = qv[bb];
        #pragma unroll
        for (int off = 16; off; off >>= 1)
            m = fmaxf(m, __shfl_xor_sync(0xffffffff, m, off));
        if (lane == 0) red[bb][wid] = m;
    }
    __syncthreads();
    #pragma unroll
    for (int bb = 0; bb < 4; bb++) {
        float qm = red[bb][0];
        #pragma unroll
        for (int w = 1; w < 8; w++) qm = fmaxf(qm, red[bb][w]);
        q_s[bb][tid] = RATIO * (__expf(qv[bb] - diagQ[ridx[bb]] - qm) + EPS);
        k_s[bb][tid] = RATIO * (__expf(kv[bb] - diagK[ridx[bb]] - kmax[bb*2 + h]) + EPS);
    }
    __syncthreads();

    int p = tid >> 4, lane16 = tid & 15;
    int bb = p >> 2, bp = p & 3;
    float acc = 0.f;
    #pragma unroll
    for (int m = 0; m < MFEAT; m += 16) acc += q_s[bb][m + lane16] * k_s[bp][m + lane16];
    #pragma unroll
    for (int off = 8; off; off >>= 1) acc += __shfl_down_sync(0xffffffff, acc, off, 16);
    if (lane16 == 0) S[bb][bp] = acc;
    __syncthreads();
    if (tid < 4) rs[tid] = S[tid][0] + S[tid][1] + S[tid][2] + S[tid][3];
    __syncthreads();

    float s00=S[0][0],s01=S[0][1],s02=S[0][2],s03=S[0][3];
    float s10=S[1][0],s11=S[1][1],s12=S[1][2],s13=S[1][3];
    float s20=S[2][0],s21=S[2][1],s22=S[2][2],s23=S[2][3];
    float s30=S[3][0],s31=S[3][1],s32=S[3][2],s33=S[3][3];
    float r0 = 1.f/rs[0], r1 = 1.f/rs[1], r2 = 1.f/rs[2], r3 = 1.f/rs[3];

    const __half2* V2 = reinterpret_cast<const __half2*>(Vh);
    __half2* C2 = reinterpret_cast<__half2*>(C);
    size_t cb2 = ((size_t)s*4096 + (size_t)h*2048) >> 1;
    int d2 = tid;
    {
        float2 v0 = __half22float2(V2[(size_t)((0*SEQ + s)*HEADS + h)*(DEPTH/2) + d2]);
        float2 v1 = __half22float2(V2[(size_t)((1*SEQ + s)*HEADS + h)*(DEPTH/2) + d2]);
        float2 v2 = __half22float2(V2[(size_t)((2*SEQ + s)*HEADS + h)*(DEPTH/2) + d2]);
        float2 v3 = __half22float2(V2[(size_t)((3*SEQ + s)*HEADS + h)*(DEPTH/2) + d2]);
        C2[cb2 + 0*256 + d2] = __floats2half2_rn((s00*v0.x + s01*v1.x + s02*v2.x + s03*v3.x) * r0,
                                                 (s00*v0.y + s01*v1.y + s02*v2.y + s03*v3.y) * r0);
        C2[cb2 + 1*256 + d2] = __floats2half2_rn((s10*v0.x + s11*v1.x + s12*v2.x + s13*v3.x) * r1,
                                                 (s10*v0.y + s11*v1.y + s12*v2.y + s13*v3.y) * r1);
        C2[cb2 + 2*256 + d2] = __floats2half2_rn((s20*v0.x + s21*v1.x + s22*v2.x + s23*v3.x) * r2,
                                                 (s20*v0.y + s21*v1.y + s22*v2.y + s23*v3.y) * r2);
        C2[cb2 + 3*256 + d2] = __floats2half2_rn((s30*v0.x + s31*v1.x + s32*v2.x + s33*v3.x) * r3,
                                                 (s30*v0.y + s31*v1.y + s32*v2.y + s33*v3.y) * r3);
    }
}

// ---------------------------------------------------------------------------
// Launch
// ---------------------------------------------------------------------------
extern "C" void kernel_launch(void* const* d_in, const int* in_sizes, int n_in,
                              void* d_out, int out_size)
{
    const float* query = (const float*)d_in[0];
    const float* key   = (const float*)d_in[1];
    const float* value = (const float*)d_in[2];
    const float* Wq = (const float*)d_in[4];
    const float* bq = (const float*)d_in[5];
    const float* Wk = (const float*)d_in[6];
    const float* bk = (const float*)d_in[7];
    const float* Wv = (const float*)d_in[8];
    const float* bv = (const float*)d_in[9];
    const float* Wo = (const float*)d_in[10];
    const float* bo = (const float*)d_in[11];
    const float* feats = (const float*)d_in[12];   // [256, 512] == [N, K]
    float* out = (float*)d_out;

    float *diagQ, *diagK, *rmxp, *kmax, *sqpQ, *sqpK;
    __half *dQh, *dKh, *A0, *A1, *A2, *Qh, *Kh, *Vh, *W0, *W1, *W2, *W3, *fh, *Ch;
    cudaGetSymbolAddress((void**)&dQh,   g_dQh);
    cudaGetSymbolAddress((void**)&dKh,   g_dKh);
    cudaGetSymbolAddress((void**)&diagQ, g_diagQ);
    cudaGetSymbolAddress((void**)&diagK, g_diagK);
    cudaGetSymbolAddress((void**)&rmxp,  g_rmxp);
    cudaGetSymbolAddress((void**)&kmax,  g_kmax);
    cudaGetSymbolAddress((void**)&sqpQ,  g_sqpQ);
    cudaGetSymbolAddress((void**)&sqpK,  g_sqpK);
    cudaGetSymbolAddress((void**)&A0,    g_A0);
    cudaGetSymbolAddress((void**)&A1,    g_A1);
    cudaGetSymbolAddress((void**)&A2,    g_A2);
    cudaGetSymbolAddress((void**)&Qh,    g_Qh);
    cudaGetSymbolAddress((void**)&Kh,    g_Kh);
    cudaGetSymbolAddress((void**)&Vh,    g_Vh);
    cudaGetSymbolAddress((void**)&W0,    g_W0);
    cudaGetSymbolAddress((void**)&W1,    g_W1);
    cudaGetSymbolAddress((void**)&W2,    g_W2);
    cudaGetSymbolAddress((void**)&W3,    g_W3);
    cudaGetSymbolAddress((void**)&fh,    g_fh);
    cudaGetSymbolAddress((void**)&Ch,    g_Ch);

    cudaFuncSetAttribute(hgemm, cudaFuncAttributeMaxDynamicSharedMemorySize, HSMEM);

    const unsigned gR2 = (ROWS2 + 255) / 256;

    // 0: all fp16 conversions in ONE launch
    {
        ConvArgs a;
        a.in3[0] = query; a.in3[1] = key; a.in3[2] = value;
        a.out3[0] = A0;   a.out3[1] = A1; a.out3[2] = A2;
        a.w[0] = Wq; a.w[1] = Wk; a.w[2] = Wv; a.w[3] = Wo;
        a.wo[0] = W0; a.wo[1] = W1; a.wo[2] = W2; a.wo[3] = W3;
        a.feats = feats; a.fh = fh;
        convert_all_kernel<<<CONV_TOTAL, 256>>>(a);
    }

    // 1: batched Q/K/V projections (one launch, z = 3)
    {
        GemmJobs jobs;
        jobs.j[0] = { A0, W0, bq, nullptr, Qh, sqpQ, nullptr };
        jobs.j[1] = { A1, W1, bk, nullptr, Kh, sqpK, nullptr };
        jobs.j[2] = { A2, W2, bv, nullptr, Vh, nullptr, nullptr };
        dim3 g(DMODEL/64, ROWS/128, 3);
        hgemm<<<g, 128, HSMEM>>>(jobs, ROWS, DMODEL, DMODEL, 1.f);
    }
    sqreduce_kernel<<<gR2, 256>>>(sqpQ, diagQ, sqpK, diagK);

    // 2: batched feature projections (z = 2), fp16 dash outputs
    {
        GemmJobs jobs;
        jobs.j[0] = { Qh, fh, nullptr, nullptr, dQh, nullptr, nullptr };
        jobs.j[1] = { Kh, fh, nullptr, nullptr, dKh, nullptr, rmxp };
        jobs.j[2] = jobs.j[0];
        dim3 g(MFEAT/64, ROWS2/128, 2);
        hgemm<<<g, 128, HSMEM>>>(jobs, ROWS2, MFEAT, DEPTH, FSCALE);
    }
    kmax_kernel<<<BATCH*HEADS, 256>>>(rmxp, kmax);

    // 3: fused q'/k' + attention mix -> fp16 concat
    attn_mix_kernel<<<SEQ*HEADS, 256>>>(dQh, dKh, diagQ, diagK, kmax, Vh, Ch);

    // 4: out = C @ Wo + bo
    {
        GemmJobs jobs;
        jobs.j[0] = { Ch, W3, bo, out, nullptr, nullptr, nullptr };
        jobs.j[1] = jobs.j[0];
        jobs.j[2] = jobs.j[0];
        dim3 g(DMODEL/64, ROWS/128, 1);
        hgemm<<<g, 128, HSMEM>>>(jobs, ROWS, DMODEL, DMODEL, 1.f);
    }
}

// round 17
// speedup vs baseline: 1.7463x; 1.7463x over previous
#include <cuda_runtime.h>
#include <cuda_fp16.h>
#include <math.h>
#include <stdint.h>

// ---------------------------------------------------------------------------
// Problem constants
// ---------------------------------------------------------------------------
#define BATCH     4
#define SEQ       4096
#define DMODEL    1024
#define HEADS     2
#define DEPTH     512
#define MFEAT     256
#define ROWS      (BATCH*SEQ)          // 16384
#define ROWS2     (ROWS*HEADS)         // 32768

#define SCALE2    0.044194173824159216f   // 1/sqrt(512)
#define FSCALE    0.21022410381342864f    // 512^{-0.25}
#define RATIO     0.0625f                 // 1/sqrt(256)
#define EPS       1e-6f

// ---------------------------------------------------------------------------
// Scratch (device globals; allocation is banned)
// ---------------------------------------------------------------------------
__device__ __half g_dQh[ (size_t)ROWS2 * MFEAT ];    // fp16 dash_q
__device__ __half g_dKh[ (size_t)ROWS2 * MFEAT ];    // fp16 dash_k
__device__ float  g_diagQ[ ROWS2 ];
__device__ float  g_diagK[ ROWS2 ];
__device__ float  g_rmxp [ 4 * ROWS2 ];              // per-colblock rowmax partials
__device__ float  g_kmax [ BATCH*HEADS ];
__device__ float  g_sqpQ[ 16 * ROWS ];               // per-colblock Σy² partials (Q)
__device__ float  g_sqpK[ 16 * ROWS ];               // (K)
__device__ __half g_A0 [ (size_t)ROWS * DMODEL ];    // fp16 query
__device__ __half g_A1 [ (size_t)ROWS * DMODEL ];    // fp16 key
__device__ __half g_A2 [ (size_t)ROWS * DMODEL ];    // fp16 value
__device__ __half g_Qh [ (size_t)ROWS * DMODEL ];    // fp16 Q
__device__ __half g_Kh [ (size_t)ROWS * DMODEL ];    // fp16 K
__device__ __half g_Vh [ (size_t)ROWS * DMODEL ];    // fp16 V
__device__ __half g_W0 [ (size_t)DMODEL * DMODEL ];  // fp16 Wq^T
__device__ __half g_W1 [ (size_t)DMODEL * DMODEL ];  // fp16 Wk^T
__device__ __half g_W2 [ (size_t)DMODEL * DMODEL ];  // fp16 Wv^T (reused for Wo^T)
__device__ __half g_fh [ (size_t)MFEAT * DEPTH ];    // fp16 feats
__device__ __half g_Ch [ (size_t)ROWS * DMODEL ];    // fp16 concat

// ---------------------------------------------------------------------------
// helpers
// ---------------------------------------------------------------------------
__device__ __forceinline__ uint32_t smem_u32(const void* p) {
    uint32_t a;
    asm("{ .reg .u64 t; cvta.to.shared.u64 t, %1; cvt.u32.u64 %0, t; }"
        : "=r"(a) : "l"(p));
    return a;
}

__device__ __forceinline__ void ldsm_x4(uint32_t& r0, uint32_t& r1,
                                        uint32_t& r2, uint32_t& r3, uint32_t addr) {
    asm volatile("ldmatrix.sync.aligned.m8n8.x4.shared.b16 {%0,%1,%2,%3}, [%4];"
                 : "=r"(r0), "=r"(r1), "=r"(r2), "=r"(r3) : "r"(addr));
}

__device__ __forceinline__ void mma_f16(float c[4], const uint32_t a[4],
                                        const uint32_t b[2]) {
    asm volatile(
        "mma.sync.aligned.m16n8k16.row.col.f32.f16.f16.f32 "
        "{%0,%1,%2,%3}, {%4,%5,%6,%7}, {%8,%9}, {%0,%1,%2,%3};"
        : "+f"(c[0]), "+f"(c[1]), "+f"(c[2]), "+f"(c[3])
        : "r"(a[0]), "r"(a[1]), "r"(a[2]), "r"(a[3]),
          "r"(b[0]), "r"(b[1]));
}

__device__ __forceinline__ void cp_async16(uint32_t smem, const void* gmem) {
    asm volatile("cp.async.cg.shared.global [%0], [%1], 16;"
                 :: "r"(smem), "l"(gmem) : "memory");
}
#define CP_COMMIT()  asm volatile("cp.async.commit_group;" ::: "memory")
#define CP_WAIT0()   asm volatile("cp.async.wait_group 0;" ::: "memory")

// ---------------------------------------------------------------------------
// Batched fp16 GEMM jobs (selected by blockIdx.z)
// ---------------------------------------------------------------------------
struct GemmJob {
    const __half* A;      // [M,K]
    const __half* Bop;    // [N,K]
    const float*  bias;   // [N] or null
    float*        C;      // fp32 out or null
    __half*       Ch;     // fp16 out or null
    float*        sq;     // per-row sum-sq partials [N/64][M] or null
    float*        rmx;    // per-row max partials [N/64][M] or null
};
struct GemmJobs { GemmJob j[3]; };

// ---------------------------------------------------------------------------
// fp16 GEMM (fp32 accumulate):  C = alpha * A(M,K) @ Bop(N,K)^T (+ bias)
//   128 threads/CTA, tile 128(M) x 64(N), warp tile 64x32 (2x2 warps),
//   2-stage cp.async pipeline, K-step 64, A-fragment double buffering.
//   Requires M%128, N%64, K%64==0, K>=128.   (R13 config — best measured)
// ---------------------------------------------------------------------------
#define ASTR   72                       // halves per row: 64 + 8 pad (144B)
#define STG_A  (128*ASTR)               // 9216 halves
#define STG_B  (64*ASTR)                // 4608 halves
#define STG_T  (STG_A + STG_B)          // 13824 halves / stage
#define HSMEM  (2 * STG_T * 2)          // bytes = 55296

__global__ __launch_bounds__(128, 4)
void hgemm(GemmJobs jobs, int M, int N, int K, float alpha)
{
    extern __shared__ __half sm[];
    const GemmJob job = jobs.j[blockIdx.z];
    const __half* __restrict__ A   = job.A;
    const __half* __restrict__ Bop = job.Bop;

    const int tid  = threadIdx.x;
    const int lane = tid & 31;
    const int wid  = tid >> 5;            // 0..3
    const int bm = blockIdx.y * 128;
    const int bn = blockIdx.x * 64;

    const int warp_m = (wid & 1) * 64;
    const int warp_n = (wid >> 1) * 32;
    const int lr = lane >> 2;
    const int lc = lane & 3;

    const uint32_t smb = smem_u32(sm);

    auto issue_stage = [&](int s, int k0) {
        const int slot = s & 1;
        const uint32_t abase = smb + (uint32_t)(slot * STG_T) * 2;
        const uint32_t bbase = abase + (uint32_t)STG_A * 2;
        #pragma unroll
        for (int c = 0; c < 8; c++) {
            int chunk = tid + 128 * c;
            int row = chunk >> 3;
            int col = (chunk & 7) * 8;
            cp_async16(abase + (uint32_t)(row * ASTR + col) * 2,
                       A + (size_t)(bm + row) * K + k0 + col);
        }
        #pragma unroll
        for (int c = 0; c < 4; c++) {
            int chunk = tid + 128 * c;
            int row = chunk >> 3;
            int col = (chunk & 7) * 8;
            cp_async16(bbase + (uint32_t)(row * ASTR + col) * 2,
                       Bop + (size_t)(bn + row) * K + k0 + col);
        }
        CP_COMMIT();
    };

    float acc[4][4][4];
    #pragma unroll
    for (int i = 0; i < 4; i++)
        #pragma unroll
        for (int j = 0; j < 4; j++)
            #pragma unroll
            for (int r = 0; r < 4; r++) acc[i][j][r] = 0.f;

    const int a_lrow = (lane & 7) + ((lane >> 3) & 1) * 8;
    const int a_lcol = (lane >> 4) * 8;
    const int b_lrow = (lane & 7) + (lane >= 16 ? 8 : 0);
    const int b_lcol = ((lane >> 3) & 1) * 8;

    const int nst = K >> 6;
    issue_stage(0, 0);

    for (int s = 0; s < nst; s++) {
        CP_WAIT0();
        __syncthreads();

        if (s + 1 < nst) issue_stage(s + 1, (s + 1) << 6);

        const __half* As = sm + (s & 1) * STG_T;
        const __half* Bs = As + STG_A;

        uint32_t fa[2][4][4];
        #pragma unroll
        for (int mi = 0; mi < 4; mi++) {
            uint32_t addr = smem_u32(
                &As[(warp_m + mi * 16 + a_lrow) * ASTR + a_lcol]);
            ldsm_x4(fa[0][mi][0], fa[0][mi][1], fa[0][mi][2], fa[0][mi][3], addr);
        }

        #pragma unroll
        for (int kk = 0; kk < 4; kk++) {
            const int pb = kk & 1;
            uint32_t fb[4][2];
            #pragma unroll
            for (int nj = 0; nj < 2; nj++) {
                uint32_t addr = smem_u32(
                    &Bs[(warp_n + nj * 16 + b_lrow) * ASTR + kk * 16 + b_lcol]);
                ldsm_x4(fb[2*nj][0], fb[2*nj][1], fb[2*nj+1][0], fb[2*nj+1][1], addr);
            }
            if (kk < 3) {
                #pragma unroll
                for (int mi = 0; mi < 4; mi++) {
                    uint32_t addr = smem_u32(
                        &As[(warp_m + mi * 16 + a_lrow) * ASTR + (kk + 1) * 16 + a_lcol]);
                    ldsm_x4(fa[pb^1][mi][0], fa[pb^1][mi][1],
                            fa[pb^1][mi][2], fa[pb^1][mi][3], addr);
                }
            }
            #pragma unroll
            for (int mi = 0; mi < 4; mi++)
                #pragma unroll
                for (int ni = 0; ni < 4; ni++)
                    mma_f16(acc[mi][ni], fa[pb][mi], fb[ni]);
        }
    }

    // epilogue (+ optional per-row Σv² / rowmax partials)
    float sA[4], sB[4], mA[4], mB[4];
    #pragma unroll
    for (int mi = 0; mi < 4; mi++) {
        sA[mi] = 0.f; sB[mi] = 0.f; mA[mi] = -1e30f; mB[mi] = -1e30f;
    }

    #pragma unroll
    for (int mi = 0; mi < 4; mi++) {
        #pragma unroll
        for (int ni = 0; ni < 4; ni++) {
            int row = bm + warp_m + mi * 16 + lr;
            int col = bn + warp_n + ni * 8 + 2 * lc;
            float b0 = job.bias ? job.bias[col]     : 0.f;
            float b1 = job.bias ? job.bias[col + 1] : 0.f;
            float2 v0 = make_float2(alpha * acc[mi][ni][0] + b0,
                                    alpha * acc[mi][ni][1] + b1);
            float2 v1 = make_float2(alpha * acc[mi][ni][2] + b0,
                                    alpha * acc[mi][ni][3] + b1);
            if (job.C) {
                *reinterpret_cast<float2*>(&job.C[(size_t)row * N + col])       = v0;
                *reinterpret_cast<float2*>(&job.C[(size_t)(row + 8) * N + col]) = v1;
            }
            if (job.Ch) {
                *reinterpret_cast<__half2*>(&job.Ch[(size_t)row * N + col]) =
                    __floats2half2_rn(v0.x, v0.y);
                *reinterpret_cast<__half2*>(&job.Ch[(size_t)(row + 8) * N + col]) =
                    __floats2half2_rn(v1.x, v1.y);
            }
            if (job.sq) {
                sA[mi] += v0.x * v0.x + v0.y * v0.y;
                sB[mi] += v1.x * v1.x + v1.y * v1.y;
            }
            if (job.rmx) {
                mA[mi] = fmaxf(mA[mi], fmaxf(v0.x, v0.y));
                mB[mi] = fmaxf(mB[mi], fmaxf(v1.x, v1.y));
            }
        }
    }

    float* smf = reinterpret_cast<float*>(sm);  // [2][128] floats
    if (job.sq) {
        #pragma unroll
        for (int mi = 0; mi < 4; mi++) {
            #pragma unroll
            for (int o = 1; o <= 2; o <<= 1) {
                sA[mi] += __shfl_xor_sync(0xffffffff, sA[mi], o);
                sB[mi] += __shfl_xor_sync(0xffffffff, sB[mi], o);
            }
        }
        __syncthreads();
        if (lc == 0) {
            #pragma unroll
            for (int mi = 0; mi < 4; mi++) {
                smf[(wid >> 1) * 128 + warp_m + mi * 16 + lr]     = sA[mi];
                smf[(wid >> 1) * 128 + warp_m + mi * 16 + lr + 8] = sB[mi];
            }
        }
        __syncthreads();
        {
            float t = smf[tid] + smf[128 + tid];
            job.sq[(size_t)blockIdx.x * M + bm + tid] = t;
        }
    }
    if (job.rmx) {
        #pragma unroll
        for (int mi = 0; mi < 4; mi++) {
            #pragma unroll
            for (int o = 1; o <= 2; o <<= 1) {
                mA[mi] = fmaxf(mA[mi], __shfl_xor_sync(0xffffffff, mA[mi], o));
                mB[mi] = fmaxf(mB[mi], __shfl_xor_sync(0xffffffff, mB[mi], o));
            }
        }
        __syncthreads();
        if (lc == 0) {
            #pragma unroll
            for (int mi = 0; mi < 4; mi++) {
                smf[(wid >> 1) * 128 + warp_m + mi * 16 + lr]     = mA[mi];
                smf[(wid >> 1) * 128 + warp_m + mi * 16 + lr + 8] = mB[mi];
            }
        }
        __syncthreads();
        {
            float t = fmaxf(smf[tid], smf[128 + tid]);
            job.rmx[(size_t)blockIdx.x * M + bm + tid] = t;
        }
    }
}

// ---------------------------------------------------------------------------
// diag reduce: diag[r*2+h] = 0.5*SCALE2 * sum_{j<8} part[(h*8+j)*ROWS + r]
// ---------------------------------------------------------------------------
__global__ __launch_bounds__(256)
void sqreduce_kernel(const float* __restrict__ partQ, float* __restrict__ diagQ,
                     const float* __restrict__ partK, float* __restrict__ diagK)
{
    int r2 = blockIdx.x * blockDim.x + threadIdx.x;
    if (r2 >= ROWS2) return;
    int r = r2 >> 1, h = r2 & 1;
    {
        const float* p = partQ + (size_t)(h * 8) * ROWS + r;
        float s = 0.f;
        #pragma unroll
        for (int j = 0; j < 8; j++) s += p[(size_t)j * ROWS];
        diagQ[r2] = 0.5f * SCALE2 * s;
    }
    {
        const float* p = partK + (size_t)(h * 8) * ROWS + r;
        float s = 0.f;
        #pragma unroll
        for (int j = 0; j < 8; j++) s += p[(size_t)j * ROWS];
        diagK[r2] = 0.5f * SCALE2 * s;
    }
}

// ---------------------------------------------------------------------------
// kmax: per (b,h) global max over sequence of dK rowmax partials (4 colblocks)
// ---------------------------------------------------------------------------
__global__ __launch_bounds__(256)
void kmax_kernel(const float* __restrict__ rmxp, float* __restrict__ kmax)
{
    int bh = blockIdx.x;
    int b  = bh >> 1, h = bh & 1;
    __shared__ float sm[256];
    float mx = -1e30f;
    for (int l = threadIdx.x; l < SEQ; l += 256) {
        int r = b * 8192 + l * 2 + h;
        #pragma unroll
        for (int cb = 0; cb < 4; cb++)
            mx = fmaxf(mx, rmxp[(size_t)cb * ROWS2 + r]);
    }
    sm[threadIdx.x] = mx;
    __syncthreads();
    for (int s = 128; s; s >>= 1) {
        if (threadIdx.x < s) sm[threadIdx.x] = fmaxf(sm[threadIdx.x], sm[threadIdx.x + s]);
        __syncthreads();
    }
    if (threadIdx.x == 0) kmax[bh] = sm[0];
}

// ---------------------------------------------------------------------------
// f32 -> fp16 elementwise convert: three tensors in one launch (blockIdx.y)
// (ternary pointer selection — no dynamic struct indexing, no local spill)
// ---------------------------------------------------------------------------
__global__ __launch_bounds__(256)
void f2h3_kernel(const float* __restrict__ i0, __half* __restrict__ o0,
                 const float* __restrict__ i1, __half* __restrict__ o1,
                 const float* __restrict__ i2, __half* __restrict__ o2, size_t n)
{
    const float* in  = (blockIdx.y == 0) ? i0 : (blockIdx.y == 1) ? i1 : i2;
    __half*      out = (blockIdx.y == 0) ? o0 : (blockIdx.y == 1) ? o1 : o2;
    size_t i = ((size_t)blockIdx.x * blockDim.x + threadIdx.x) * 8;
    if (i >= n) return;
    float4 v0 = *reinterpret_cast<const float4*>(in + i);
    float4 v1 = *reinterpret_cast<const float4*>(in + i + 4);
    __half h[8];
    h[0]=__float2half_rn(v0.x); h[1]=__float2half_rn(v0.y);
    h[2]=__float2half_rn(v0.z); h[3]=__float2half_rn(v0.w);
    h[4]=__float2half_rn(v1.x); h[5]=__float2half_rn(v1.y);
    h[6]=__float2half_rn(v1.z); h[7]=__float2half_rn(v1.w);
    *reinterpret_cast<uint4*>(out + i) = *reinterpret_cast<uint4*>(h);
}

__global__ __launch_bounds__(256)
void f2h_kernel(const float* __restrict__ in, __half* __restrict__ out, size_t n)
{
    size_t i = ((size_t)blockIdx.x * blockDim.x + threadIdx.x) * 8;
    if (i >= n) return;
    float4 v0 = *reinterpret_cast<const float4*>(in + i);
    float4 v1 = *reinterpret_cast<const float4*>(in + i + 4);
    __half h[8];
    h[0]=__float2half_rn(v0.x); h[1]=__float2half_rn(v0.y);
    h[2]=__float2half_rn(v0.z); h[3]=__float2half_rn(v0.w);
    h[4]=__float2half_rn(v1.x); h[5]=__float2half_rn(v1.y);
    h[6]=__float2half_rn(v1.z); h[7]=__float2half_rn(v1.w);
    *reinterpret_cast<uint4*>(out + i) = *reinterpret_cast<uint4*>(h);
}

// ---------------------------------------------------------------------------
// transpose + convert: three square weights in one launch (blockIdx.z)
// ---------------------------------------------------------------------------
__global__ __launch_bounds__(256)
void tconv3_kernel(const float* __restrict__ w0, __half* __restrict__ o0,
                   const float* __restrict__ w1, __half* __restrict__ o1,
                   const float* __restrict__ w2, __half* __restrict__ o2)
{
    const float* in  = (blockIdx.z == 0) ? w0 : (blockIdx.z == 1) ? w1 : w2;
    __half*      out = (blockIdx.z == 0) ? o0 : (blockIdx.z == 1) ? o1 : o2;
    __shared__ float tile[32][33];
    int bx = blockIdx.x * 32;
    int by = blockIdx.y * 32;
    int tx = threadIdx.x & 31;
    int ty = threadIdx.x >> 5;
    #pragma unroll
    for (int i = 0; i < 32; i += 8)
        tile[ty + i][tx] = in[(size_t)(by + ty + i) * DMODEL + bx + tx];
    __syncthreads();
    #pragma unroll
    for (int i = 0; i < 32; i += 8)
        out[(size_t)(bx + ty + i) * DMODEL + by + tx] = __float2half_rn(tile[tx][ty + i]);
}

__global__ __launch_bounds__(256)
void tconv_kernel(const float* __restrict__ in, __half* __restrict__ out,
                  int R, int Cin)
{
    __shared__ float tile[32][33];
    int bx = blockIdx.x * 32;
    int by = blockIdx.y * 32;
    int tx = threadIdx.x & 31;
    int ty = threadIdx.x >> 5;
    #pragma unroll
    for (int i = 0; i < 32; i += 8)
        tile[ty + i][tx] = in[(size_t)(by + ty + i) * Cin + bx + tx];
    __syncthreads();
    #pragma unroll
    for (int i = 0; i < 32; i += 8)
        out[(size_t)(bx + ty + i) * R + by + tx] = __float2half_rn(tile[tx][ty + i]);
}

// ---------------------------------------------------------------------------
// Attention mix (fused q'/k'): per (s,h) block. fp16 dash in, __expf.
// ---------------------------------------------------------------------------
__global__ __launch_bounds__(256)
void attn_mix_kernel(const __half* __restrict__ dQ, const __half* __restrict__ dK,
                     const float* __restrict__ diagQ, const float* __restrict__ diagK,
                     const float* __restrict__ kmax,
                     const __half* __restrict__ Vh, __half* __restrict__ C)
{
    int blk = blockIdx.x;
    int s = blk >> 1, h = blk & 1;
    __shared__ float q_s[4][MFEAT];
    __shared__ float k_s[4][MFEAT];
    __shared__ float red[4][8];
    __shared__ float S[4][4];
    __shared__ float rs[4];
    int tid = threadIdx.x;
    int wid = tid >> 5, lane = tid & 31;

    float qv[4], kv[4];
    int ridx[4];
    #pragma unroll
    for (int bb = 0; bb < 4; bb++) {
        size_t r = (size_t)((bb*SEQ + s)*HEADS + h);
        ridx[bb] = (int)r;
        qv[bb] = __half2float(dQ[r*MFEAT + tid]);
        kv[bb] = __half2float(dK[r*MFEAT + tid]);
    }
    #pragma unroll
    for (int bb = 0; bb < 4; bb++) {
        float m = qv[bb];
        #pragma unroll
        for (int off = 16; off; off >>= 1)
            m = fmaxf(m, __shfl_xor_sync(0xffffffff, m, off));
        if (lane == 0) red[bb][wid] = m;
    }
    __syncthreads();
    #pragma unroll
    for (int bb = 0; bb < 4; bb++) {
        float qm = red[bb][0];
        #pragma unroll
        for (int w = 1; w < 8; w++) qm = fmaxf(qm, red[bb][w]);
        q_s[bb][tid] = RATIO * (__expf(qv[bb] - diagQ[ridx[bb]] - qm) + EPS);
        k_s[bb][tid] = RATIO * (__expf(kv[bb] - diagK[ridx[bb]] - kmax[bb*2 + h]) + EPS);
    }
    __syncthreads();

    int p = tid >> 4, lane16 = tid & 15;
    int bb = p >> 2, bp = p & 3;
    float acc = 0.f;
    #pragma unroll
    for (int m = 0; m < MFEAT; m += 16) acc += q_s[bb][m + lane16] * k_s[bp][m + lane16];
    #pragma unroll
    for (int off = 8; off; off >>= 1) acc += __shfl_down_sync(0xffffffff, acc, off, 16);
    if (lane16 == 0) S[bb][bp] = acc;
    __syncthreads();
    if (tid < 4) rs[tid] = S[tid][0] + S[tid][1] + S[tid][2] + S[tid][3];
    __syncthreads();

    float s00=S[0][0],s01=S[0][1],s02=S[0][2],s03=S[0][3];
    float s10=S[1][0],s11=S[1][1],s12=S[1][2],s13=S[1][3];
    float s20=S[2][0],s21=S[2][1],s22=S[2][2],s23=S[2][3];
    float s30=S[3][0],s31=S[3][1],s32=S[3][2],s33=S[3][3];
    float r0 = 1.f/rs[0], r1 = 1.f/rs[1], r2 = 1.f/rs[2], r3 = 1.f/rs[3];

    const __half2* V2 = reinterpret_cast<const __half2*>(Vh);
    __half2* C2 = reinterpret_cast<__half2*>(C);
    size_t cb2 = ((size_t)s*4096 + (size_t)h*2048) >> 1;
    int d2 = tid;
    {
        float2 v0 = __half22float2(V2[(size_t)((0*SEQ + s)*HEADS + h)*(DEPTH/2) + d2]);
        float2 v1 = __half22float2(V2[(size_t)((1*SEQ + s)*HEADS + h)*(DEPTH/2) + d2]);
        float2 v2 = __half22float2(V2[(size_t)((2*SEQ + s)*HEADS + h)*(DEPTH/2) + d2]);
        float2 v3 = __half22float2(V2[(size_t)((3*SEQ + s)*HEADS + h)*(DEPTH/2) + d2]);
        C2[cb2 + 0*256 + d2] = __floats2half2_rn((s00*v0.x + s01*v1.x + s02*v2.x + s03*v3.x) * r0,
                                                 (s00*v0.y + s01*v1.y + s02*v2.y + s03*v3.y) * r0);
        C2[cb2 + 1*256 + d2] = __floats2half2_rn((s10*v0.x + s11*v1.x + s12*v2.x + s13*v3.x) * r1,
                                                 (s10*v0.y + s11*v1.y + s12*v2.y + s13*v3.y) * r1);
        C2[cb2 + 2*256 + d2] = __floats2half2_rn((s20*v0.x + s21*v1.x + s22*v2.x + s23*v3.x) * r2,
                                                 (s20*v0.y + s21*v1.y + s22*v2.y + s23*v3.y) * r2);
        C2[cb2 + 3*256 + d2] = __floats2half2_rn((s30*v0.x + s31*v1.x + s32*v2.x + s33*v3.x) * r3,
                                                 (s30*v0.y + s31*v1.y + s32*v2.y + s33*v3.y) * r3);
    }
}

// ---------------------------------------------------------------------------
// Launch
// ---------------------------------------------------------------------------
extern "C" void kernel_launch(void* const* d_in, const int* in_sizes, int n_in,
                              void* d_out, int out_size)
{
    const float* query = (const float*)d_in[0];
    const float* key   = (const float*)d_in[1];
    const float* value = (const float*)d_in[2];
    const float* Wq = (const float*)d_in[4];
    const float* bq = (const float*)d_in[5];
    const float* Wk = (const float*)d_in[6];
    const float* bk = (const float*)d_in[7];
    const float* Wv = (const float*)d_in[8];
    const float* bv = (const float*)d_in[9];
    const float* Wo = (const float*)d_in[10];
    const float* bo = (const float*)d_in[11];
    const float* feats = (const float*)d_in[12];   // [256, 512] == [N, K]
    float* out = (float*)d_out;

    float *diagQ, *diagK, *rmxp, *kmax, *sqpQ, *sqpK;
    __half *dQh, *dKh, *A0, *A1, *A2, *Qh, *Kh, *Vh, *W0, *W1, *W2, *fh, *Ch;
    cudaGetSymbolAddress((void**)&dQh,   g_dQh);
    cudaGetSymbolAddress((void**)&dKh,   g_dKh);
    cudaGetSymbolAddress((void**)&diagQ, g_diagQ);
    cudaGetSymbolAddress((void**)&diagK, g_diagK);
    cudaGetSymbolAddress((void**)&rmxp,  g_rmxp);
    cudaGetSymbolAddress((void**)&kmax,  g_kmax);
    cudaGetSymbolAddress((void**)&sqpQ,  g_sqpQ);
    cudaGetSymbolAddress((void**)&sqpK,  g_sqpK);
    cudaGetSymbolAddress((void**)&A0,    g_A0);
    cudaGetSymbolAddress((void**)&A1,    g_A1);
    cudaGetSymbolAddress((void**)&A2,    g_A2);
    cudaGetSymbolAddress((void**)&Qh,    g_Qh);
    cudaGetSymbolAddress((void**)&Kh,    g_Kh);
    cudaGetSymbolAddress((void**)&Vh,    g_Vh);
    cudaGetSymbolAddress((void**)&W0,    g_W0);
    cudaGetSymbolAddress((void**)&W1,    g_W1);
    cudaGetSymbolAddress((void**)&W2,    g_W2);
    cudaGetSymbolAddress((void**)&fh,    g_fh);
    cudaGetSymbolAddress((void**)&Ch,    g_Ch);

    cudaFuncSetAttribute(hgemm, cudaFuncAttributeMaxDynamicSharedMemorySize, HSMEM);

    const size_t NELEM = (size_t)ROWS * DMODEL;
    const unsigned gConv = (unsigned)((NELEM/8 + 255) / 256);
    const unsigned gR2   = (ROWS2 + 255) / 256;

    // 0: all fp16 conversions (inputs batched, weights batched, feats)
    {
        dim3 g(gConv, 3);
        f2h3_kernel<<<g, 256>>>(query, A0, key, A1, value, A2, NELEM);
        dim3 gT(DMODEL/32, DMODEL/32, 3);
        tconv3_kernel<<<gT, 256>>>(Wq, W0, Wk, W1, Wv, W2);
        f2h_kernel<<<(unsigned)((MFEAT*DEPTH/8 + 255)/256), 256>>>(feats, fh, MFEAT*DEPTH);
    }

    // 1: batched Q/K/V projections (one launch, z = 3)
    {
        GemmJobs jobs;
        jobs.j[0] = { A0, W0, bq, nullptr, Qh, sqpQ, nullptr };
        jobs.j[1] = { A1, W1, bk, nullptr, Kh, sqpK, nullptr };
        jobs.j[2] = { A2, W2, bv, nullptr, Vh, nullptr, nullptr };
        dim3 g(DMODEL/64, ROWS/128, 3);
        hgemm<<<g, 128, HSMEM>>>(jobs, ROWS, DMODEL, DMODEL, 1.f);
    }
    sqreduce_kernel<<<gR2, 256>>>(sqpQ, diagQ, sqpK, diagK);

    // 2: batched feature projections (z = 2), fp16 dash outputs
    {
        GemmJobs jobs;
        jobs.j[0] = { Qh, fh, nullptr, nullptr, dQh, nullptr, nullptr };
        jobs.j[1] = { Kh, fh, nullptr, nullptr, dKh, nullptr, rmxp };
        jobs.j[2] = jobs.j[0];
        dim3 g(MFEAT/64, ROWS2/128, 2);
        hgemm<<<g, 128, HSMEM>>>(jobs, ROWS2, MFEAT, DEPTH, FSCALE);
    }
    kmax_kernel<<<BATCH*HEADS, 256>>>(rmxp, kmax);

    // 3: fused q'/k' + attention mix -> fp16 concat
    attn_mix_kernel<<<SEQ*HEADS, 256>>>(dQh, dKh, diagQ, diagK, kmax, Vh, Ch);

    // 4: out = C @ Wo + bo
    tconv_kernel<<<dim3(DMODEL/32, DMODEL/32), 256>>>(Wo, W2, DMODEL, DMODEL);
    {
        GemmJobs jobs;
        jobs.j[0] = { Ch, W2, bo, out, nullptr, nullptr, nullptr };
        jobs.j[1] = jobs.j[0];
        jobs.j[2] = jobs.j[0];
        dim3 g(DMODEL/64, ROWS/128, 1);
        hgemm<<<g, 128, HSMEM>>>(jobs, ROWS, DMODEL, DMODEL, 1.f);
    }
}